// round 1
// baseline (speedup 1.0000x reference)
#include <cuda_runtime.h>
#include <math.h>

#define B_TOT 128
#define NWIN  32
#define NTOK  343
#define HEADS 6
#define HD    32
#define CDIM  192
#define C3    576
#define MTOT  (B_TOT * NTOK)   // 43904

// Scratch (no allocations allowed)
__device__ float g_qkv[MTOT * C3];          // 101.2 MB
__device__ float g_ao [MTOT * CDIM];        //  33.7 MB
__device__ float g_bias[HEADS * NTOK * NTOK]; // 2.8 MB

// ---------------------------------------------------------------------------
// Bias gather: g_bias[h][i][j] = table[rel[i*N+j]*H + h]
// ---------------------------------------------------------------------------
__global__ void bias_kernel(const float* __restrict__ table,
                            const int* __restrict__ rel) {
    int idx = blockIdx.x * blockDim.x + threadIdx.x;
    const int total = HEADS * NTOK * NTOK;
    if (idx >= total) return;
    int h  = idx / (NTOK * NTOK);
    int ij = idx % (NTOK * NTOK);
    g_bias[idx] = table[rel[ij] * HEADS + h];
}

// ---------------------------------------------------------------------------
// C[m][n] = sum_k X[m][k] * W[n][k] + bias[n]
// M % 64 == 0, N % 64 == 0, K % 16 == 0 (true for both GEMMs here)
// ---------------------------------------------------------------------------
__global__ __launch_bounds__(256) void gemm_xwT(const float* __restrict__ X,
                                                const float* __restrict__ W,
                                                const float* __restrict__ bias,
                                                float* __restrict__ C,
                                                int M, int N, int K) {
    __shared__ float sA[64][17];
    __shared__ float sB[16][64];
    const int m0 = blockIdx.y * 64;
    const int n0 = blockIdx.x * 64;
    const int t  = threadIdx.x;
    const int tr = t / 16, tc = t % 16;

    float acc[4][4] = {};
    for (int k0 = 0; k0 < K; k0 += 16) {
        {   // A tile: 64x16, 4 contiguous floats per thread
            int idx = t * 4;
            int m = idx / 16, k = idx % 16;
            float4 v = *(const float4*)&X[(size_t)(m0 + m) * K + k0 + k];
            sA[m][k] = v.x; sA[m][k + 1] = v.y; sA[m][k + 2] = v.z; sA[m][k + 3] = v.w;
        }
        {   // B tile: sB[k][n] = W[n0+n][k0+k]
            int idx = t * 4;
            int n = idx / 16, k = idx % 16;
            float4 v = *(const float4*)&W[(size_t)(n0 + n) * K + k0 + k];
            sB[k][n] = v.x; sB[k + 1][n] = v.y; sB[k + 2][n] = v.z; sB[k + 3][n] = v.w;
        }
        __syncthreads();
        #pragma unroll
        for (int k = 0; k < 16; k++) {
            float a[4];
            #pragma unroll
            for (int i = 0; i < 4; i++) a[i] = sA[tr * 4 + i][k];
            float4 b4 = *(const float4*)&sB[k][tc * 4];
            float b[4] = {b4.x, b4.y, b4.z, b4.w};
            #pragma unroll
            for (int i = 0; i < 4; i++)
                #pragma unroll
                for (int j = 0; j < 4; j++)
                    acc[i][j] += a[i] * b[j];
        }
        __syncthreads();
    }
    #pragma unroll
    for (int i = 0; i < 4; i++) {
        int m = m0 + tr * 4 + i;
        int n = n0 + tc * 4;
        float4 r = make_float4(acc[i][0] + bias[n],
                               acc[i][1] + bias[n + 1],
                               acc[i][2] + bias[n + 2],
                               acc[i][3] + bias[n + 3]);
        *(float4*)&C[(size_t)m * N + n] = r;
    }
}

// ---------------------------------------------------------------------------
// Attention: one block per (b*H + h, 64-query tile)
// ---------------------------------------------------------------------------
#define TQ 64
#define TK 64
#define SQ_STR 33
#define SK_STR 33
#define SV_STR 32
#define SS_STR 344
// smem floats: 64*33 + 64*33 + 64*32 + 64*344 = 28288 -> 113152 bytes
#define ATTN_SMEM_BYTES ((64*SQ_STR + 64*SK_STR + 64*SV_STR + 64*SS_STR) * 4)

__global__ __launch_bounds__(256, 2) void attn_kernel(const float* __restrict__ qkv,
                                                      const float* __restrict__ mask,
                                                      float* __restrict__ ao) {
    extern __shared__ float smem[];
    float* sQ = smem;
    float* sK = sQ + 64 * SQ_STR;
    float* sV = sK + 64 * SK_STR;
    float* sS = sV + 64 * SV_STR;

    const int bh = blockIdx.y;
    const int b  = bh / HEADS;
    const int h  = bh % HEADS;
    const int qt = blockIdx.x;
    const int q0 = qt * TQ;
    const int w  = b % NWIN;
    const int t  = threadIdx.x;
    const float scale = rsqrtf((float)HD);

    // ---- load Q tile (scaled) ----
    #pragma unroll
    for (int it = 0; it < 2; it++) {
        int idx = (it * 256 + t) * 4;
        int r = idx / HD, d = idx % HD;
        int n = q0 + r;
        float4 v = make_float4(0.f, 0.f, 0.f, 0.f);
        if (n < NTOK)
            v = *(const float4*)&qkv[(size_t)(b * NTOK + n) * C3 + h * HD + d];
        sQ[r * SQ_STR + d]     = v.x * scale;
        sQ[r * SQ_STR + d + 1] = v.y * scale;
        sQ[r * SQ_STR + d + 2] = v.z * scale;
        sQ[r * SQ_STR + d + 3] = v.w * scale;
    }

    const int tr = t / 16, tc = t % 16;

    // ---- S = QK^T + bias + mask, tiled over keys ----
    for (int kt = 0; kt < (NTOK + TK - 1) / TK; kt++) {
        const int k0 = kt * TK;
        __syncthreads();
        #pragma unroll
        for (int it = 0; it < 2; it++) {
            int idx = (it * 256 + t) * 4;
            int r = idx / HD, d = idx % HD;
            int n = k0 + r;
            float4 v = make_float4(0.f, 0.f, 0.f, 0.f);
            if (n < NTOK)
                v = *(const float4*)&qkv[(size_t)(b * NTOK + n) * C3 + CDIM + h * HD + d];
            sK[r * SK_STR + d]     = v.x;
            sK[r * SK_STR + d + 1] = v.y;
            sK[r * SK_STR + d + 2] = v.z;
            sK[r * SK_STR + d + 3] = v.w;
        }
        __syncthreads();

        float acc[4][4] = {};
        #pragma unroll
        for (int d = 0; d < HD; d++) {
            float a[4], bb[4];
            #pragma unroll
            for (int i = 0; i < 4; i++) a[i]  = sQ[(4 * tr + i) * SQ_STR + d];
            #pragma unroll
            for (int j = 0; j < 4; j++) bb[j] = sK[(4 * tc + j) * SK_STR + d];
            #pragma unroll
            for (int i = 0; i < 4; i++)
                #pragma unroll
                for (int j = 0; j < 4; j++)
                    acc[i][j] += a[i] * bb[j];
        }
        #pragma unroll
        for (int i = 0; i < 4; i++) {
            int ig = q0 + 4 * tr + i;
            if (ig >= NTOK) continue;
            #pragma unroll
            for (int j = 0; j < 4; j++) {
                int jg = k0 + 4 * tc + j;
                if (jg >= NTOK) continue;
                float bv = g_bias[((size_t)h * NTOK + ig) * NTOK + jg];
                float mv = mask[((size_t)w * NTOK + ig) * NTOK + jg];
                sS[(4 * tr + i) * SS_STR + jg] = acc[i][j] + bv + mv;
            }
        }
    }
    __syncthreads();

    // ---- softmax: warp per row (8 warps x 8 rows) ----
    const int warp = t / 32, lane = t % 32;
    for (int rr = 0; rr < 8; rr++) {
        int r = warp * 8 + rr;
        float* row = &sS[r * SS_STR];
        if (q0 + r >= NTOK) {
            for (int j = lane; j < NTOK; j += 32) row[j] = 0.f;
            continue;
        }
        float mx = -1e30f;
        for (int j = lane; j < NTOK; j += 32) mx = fmaxf(mx, row[j]);
        #pragma unroll
        for (int o = 16; o; o >>= 1) mx = fmaxf(mx, __shfl_xor_sync(0xffffffffu, mx, o));
        float sum = 0.f;
        for (int j = lane; j < NTOK; j += 32) {
            float e = __expf(row[j] - mx);
            row[j] = e;
            sum += e;
        }
        #pragma unroll
        for (int o = 16; o; o >>= 1) sum += __shfl_xor_sync(0xffffffffu, sum, o);
        float inv = 1.f / sum;
        for (int j = lane; j < NTOK; j += 32) row[j] *= inv;
    }
    __syncthreads();

    // ---- O = P @ V, tiled over keys ----
    // thread t: rows {tr2, tr2+32}, dims {4*tc2 .. 4*tc2+3}
    const int tr2 = t / 8;
    const int tc2 = t % 8;
    float oacc[2][4] = {};
    for (int kt = 0; kt < (NTOK + TK - 1) / TK; kt++) {
        const int k0 = kt * TK;
        #pragma unroll
        for (int it = 0; it < 2; it++) {
            int idx = (it * 256 + t) * 4;
            int r = idx / HD, d = idx % HD;
            int n = k0 + r;
            float4 v = make_float4(0.f, 0.f, 0.f, 0.f);
            if (n < NTOK)
                v = *(const float4*)&qkv[(size_t)(b * NTOK + n) * C3 + 2 * CDIM + h * HD + d];
            *(float4*)&sV[r * SV_STR + d] = v;
        }
        __syncthreads();
        const int kn = (NTOK - k0) < TK ? (NTOK - k0) : TK;
        for (int j = 0; j < kn; j++) {
            float p0 = sS[tr2 * SS_STR + k0 + j];
            float p1 = sS[(tr2 + 32) * SS_STR + k0 + j];
            float4 v4 = *(const float4*)&sV[j * SV_STR + tc2 * 4];
            oacc[0][0] += p0 * v4.x; oacc[0][1] += p0 * v4.y;
            oacc[0][2] += p0 * v4.z; oacc[0][3] += p0 * v4.w;
            oacc[1][0] += p1 * v4.x; oacc[1][1] += p1 * v4.y;
            oacc[1][2] += p1 * v4.z; oacc[1][3] += p1 * v4.w;
        }
        __syncthreads();
    }

    #pragma unroll
    for (int ri = 0; ri < 2; ri++) {
        int n = q0 + tr2 + ri * 32;
        if (n < NTOK) {
            *(float4*)&ao[(size_t)(b * NTOK + n) * CDIM + h * HD + tc2 * 4] =
                make_float4(oacc[ri][0], oacc[ri][1], oacc[ri][2], oacc[ri][3]);
        }
    }
}

// ---------------------------------------------------------------------------
extern "C" void kernel_launch(void* const* d_in, const int* in_sizes, int n_in,
                              void* d_out, int out_size) {
    const float* x      = (const float*)d_in[0];
    const float* mask   = (const float*)d_in[1];
    const float* qkv_w  = (const float*)d_in[2];
    const float* qkv_b  = (const float*)d_in[3];
    const float* proj_w = (const float*)d_in[4];
    const float* proj_b = (const float*)d_in[5];
    const float* rpb    = (const float*)d_in[6];
    const int*   rel    = (const int*)d_in[7];
    float* out = (float*)d_out;

    float *p_qkv = nullptr, *p_ao = nullptr;
    cudaGetSymbolAddress((void**)&p_qkv, g_qkv);
    cudaGetSymbolAddress((void**)&p_ao,  g_ao);

    static bool attr_set = false;
    if (!attr_set) {
        cudaFuncSetAttribute(attn_kernel, cudaFuncAttributeMaxDynamicSharedMemorySize,
                             ATTN_SMEM_BYTES);
        attr_set = true;
    }

    // 1) bias gather
    {
        int total = HEADS * NTOK * NTOK;
        bias_kernel<<<(total + 255) / 256, 256>>>(rpb, rel);
    }
    // 2) QKV GEMM: (43904 x 192) @ (192 x 576)^T
    {
        dim3 grid(C3 / 64, MTOT / 64);
        gemm_xwT<<<grid, 256>>>(x, qkv_w, qkv_b, p_qkv, MTOT, C3, CDIM);
    }
    // 3) attention
    {
        dim3 grid((NTOK + TQ - 1) / TQ, B_TOT * HEADS);
        attn_kernel<<<grid, 256, ATTN_SMEM_BYTES>>>(p_qkv, mask, p_ao);
    }
    // 4) proj GEMM: (43904 x 192) @ (192 x 192)^T
    {
        dim3 grid(CDIM / 64, MTOT / 64);
        gemm_xwT<<<grid, 256>>>(p_ao, proj_w, proj_b, out, MTOT, CDIM, CDIM);
    }
}